// round 16
// baseline (speedup 1.0000x reference)
#include <cuda_runtime.h>
#include <cstdint>

// LambdaLoss: B=4096 lists, L=128 items.
// loss = mean over valid lists of
//        [ sum_{i,j: rel_i>rel_j} (rel_i-rel_j)*softplus(-(p_i-p_j)) / cnt ]
//
// R16 — telescoped prefix products (R15) + zero-padded aligned segments +
// packed f32x2 inner math.
//   softplus(-(p_w-p_l)) = ln(1 + e_l*rec_w); counting-sort by rel.
//   For winner (sorted idx t, class ct):
//     contrib = sum_{m=1..ct} log2 PROD_{i<segEnd(m)} (1 + recS*e_i)
//   Padding each class segment to an 8-aligned boundary with e=0 entries
//   (factor == exactly 1) removes ALL scalar head/tail loops; the walk is a
//   single unrolled 8-wide bulk loop per segment with uniform trip counts.
//   Factors built 2-at-a-time with fma.rn.f32x2 / mul.rn.f32x2 (sm_103a
//   packed fp32 pipe); dual scalar chains + exponent harvesting keep the
//   product in range; ONE lg2 per checkpoint (<=4/thread), 0 MUFU per pair.

#define LL_B   4096
#define LL_L   128
#define LOG2E  1.4426950408889634f
#define LN2    0.6931471805599453f
#define PADCAP 168   // 128 + 5*7 worst-case padding, rounded up

__device__ float g_sum   = 0.0f;
__device__ int   g_valid = 0;
__device__ int   g_done  = 0;

__device__ __forceinline__ float fast_ex2(float x) {
    float r; asm("ex2.approx.f32 %0, %1;" : "=f"(r) : "f"(x)); return r;
}
__device__ __forceinline__ float fast_lg2(float x) {
    float r; asm("lg2.approx.f32 %0, %1;" : "=f"(r) : "f"(x)); return r;
}

typedef unsigned long long ull;
__device__ __forceinline__ ull pack2(float lo, float hi) {
    ull d; asm("mov.b64 %0, {%1, %2};" : "=l"(d) : "f"(lo), "f"(hi)); return d;
}
__device__ __forceinline__ void unpack2(ull d, float& lo, float& hi) {
    asm("mov.b64 {%0, %1}, %2;" : "=f"(lo), "=f"(hi) : "l"(d));
}
__device__ __forceinline__ ull fma2(ull a, ull b, ull c) {
    ull d; asm("fma.rn.f32x2 %0, %1, %2, %3;" : "=l"(d) : "l"(a), "l"(b), "l"(c)); return d;
}
__device__ __forceinline__ ull mul2(ull a, ull b) {
    ull d; asm("mul.rn.f32x2 %0, %1, %2;" : "=l"(d) : "l"(a), "l"(b)); return d;
}

// extract exponent into expo, renormalize mantissa to [1,2)
#define HARVEST(P)                                                        \
    {                                                                     \
        const unsigned _u = __float_as_uint(P);                           \
        expo += (int)(_u >> 23) - 127;                                    \
        (P) = __uint_as_float((_u & 0x007fffffu) | 0x3f800000u);          \
    }

__global__ __launch_bounds__(128) void ll_main_kernel(
    const float* __restrict__ pred,
    const float* __restrict__ rel,
    float* __restrict__ out)
{
    __shared__ __align__(16) float SeP[PADCAP]; // padded e by class segment
    __shared__ float Srec[LL_L];                // rec by (unpadded) sorted idx
    __shared__ int   hist[8];
    __shared__ int   rankc[8];
    __shared__ int   cumB[6];                   // unpadded class boundaries
    __shared__ int   PB[6];                     // padded (8-aligned) boundaries
    __shared__ float wsum[4];

    const int t    = threadIdx.x;
    const int list = blockIdx.x;

    const float p = pred[list * LL_L + t];
    const float r = rel [list * LL_L + t];
    const int   c = (int)r;                     // rel in {0..4}
    const float q = p * LOG2E;
    const float e  = fast_ex2(q);
    const float rc = fast_ex2(-q);

    if (t < 8) { hist[t] = 0; rankc[t] = 0; }
    SeP[t] = 0.0f;                              // zero-fill incl. padding
    if (t + 128 < PADCAP) SeP[t + 128] = 0.0f;
    __syncthreads();
    atomicAdd(&hist[c], 1);
    __syncthreads();
    if (t == 0) {
        int a = 0, pb = 0;
#pragma unroll
        for (int cc = 0; cc < 5; cc++) {
            cumB[cc] = a;  PB[cc] = pb;
            a  += hist[cc];
            pb += (hist[cc] + 7) & ~7;          // 8-aligned padded length
        }
        cumB[5] = a;  PB[5] = pb;
    }
    __syncthreads();
    {
        const int rk = atomicAdd(&rankc[c], 1);
        SeP [PB[c]   + rk] = e;                 // losers table (padded)
        Srec[cumB[c] + rk] = rc;                // winners table (compact)
    }
    __syncthreads();

    // thread t = WINNER role of sorted item t
    const float recS = Srec[t];
    const int b1 = cumB[1], b2 = cumB[2], b3 = cumB[3], b4 = cumB[4];
    const int ct = (t >= b1) + (t >= b2) + (t >= b3) + (t >= b4);

    const ull rec2 = pack2(recS, recS);
    const ull one2 = pack2(1.0f, 1.0f);

    float acc = 0.0f;
    float p0 = 1.0f, p1 = 1.0f;
    int   expo = 0;
    int   j = 0;

#pragma unroll
    for (int m = 1; m <= 4; m++) {
        // stop when no lane in this warp needs checkpoint m or beyond
        if (__all_sync(0xffffffffu, ct < m)) break;

        const int j1 = PB[m];                   // 8-aligned, block-uniform
        while (j < j1) {
            const float4 va = *reinterpret_cast<const float4*>(&SeP[j]);
            const float4 vb = *reinterpret_cast<const float4*>(&SeP[j + 4]);
            const ull fa01 = fma2(rec2, pack2(va.x, va.y), one2);
            const ull fa23 = fma2(rec2, pack2(va.z, va.w), one2);
            const ull fb01 = fma2(rec2, pack2(vb.x, vb.y), one2);
            const ull fb23 = fma2(rec2, pack2(vb.z, vb.w), one2);
            const ull ma = mul2(fa01, fa23);    // {x0*x2, x1*x3}
            const ull mb = mul2(fb01, fb23);    // {y0*y2, y1*y3}
            float ga0, ga1, gb0, gb1;
            unpack2(ma, ga0, ga1);
            unpack2(mb, gb0, gb1);
            p0 *= ga0 * gb0;                    // 4 factors -> < 2^67
            p1 *= ga1 * gb1;
            HARVEST(p0)
            HARVEST(p1)
            j += 8;
        }
        // checkpoint m: current prefix log, added iff this winner needs it
        if (ct >= m)
            acc += (float)expo + fast_lg2(p0 * p1);   // p0*p1 in [1,4)
    }

    // block reduction (4 warps)
#pragma unroll
    for (int off = 16; off; off >>= 1)
        acc += __shfl_xor_sync(0xffffffffu, acc, off);
    if ((t & 31) == 0) wsum[t >> 5] = acc;
    __syncthreads();

    if (t == 0) {
        const float s = (wsum[0] + wsum[1] + wsum[2] + wsum[3]) * LN2;
        const int n0 = hist[0], n1 = hist[1], n2 = hist[2];
        const int n3 = hist[3], n4 = hist[4];
        const int cnt = n1 * n0
                      + n2 * (n0 + n1)
                      + n3 * (n0 + n1 + n2)
                      + n4 * (n0 + n1 + n2 + n3);
        if (cnt > 0) {
            atomicAdd(&g_sum, s / (float)cnt);
            atomicAdd(&g_valid, 1);
        }
        __threadfence();
        const int prev = atomicAdd(&g_done, 1);
        if (prev == gridDim.x - 1) {
            const float gs = g_sum;
            const int   gv = g_valid;
            out[0] = (gv > 0) ? (gs / (float)gv) : 0.0f;
            g_sum   = 0.0f;
            g_valid = 0;
            g_done  = 0;
        }
    }
}

extern "C" void kernel_launch(void* const* d_in, const int* in_sizes, int n_in,
                              void* d_out, int out_size)
{
    const float* pred = (const float*)d_in[0];
    const float* rel  = (const float*)d_in[1];
    float* out = (float*)d_out;

    ll_main_kernel<<<LL_B, LL_L>>>(pred, rel, out);
}